// round 1
// baseline (speedup 1.0000x reference)
#include <cuda_runtime.h>
#include <math.h>

// Stage-1 result: gated = sigmoid(q @ W^T + b), D <= 8192 floats of scratch.
__device__ float g_gated[8192];

// ---------------------------------------------------------------------------
// Kernel 1: gated[j] = sigmoid(dot(query, W[j,:]) + b[j])
// One warp per output row j. W row-major [D, D], rows contiguous.
// ---------------------------------------------------------------------------
__global__ void gate_kernel(const float* __restrict__ q,
                            const float* __restrict__ W,
                            const float* __restrict__ b,
                            int D) {
    int warp = (blockIdx.x * blockDim.x + threadIdx.x) >> 5;
    int lane = threadIdx.x & 31;
    if (warp >= D) return;

    const float4* w4 = reinterpret_cast<const float4*>(W + (size_t)warp * D);
    const float4* q4 = reinterpret_cast<const float4*>(q);
    int D4 = D >> 2;

    float s = 0.0f;
    #pragma unroll 4
    for (int i = lane; i < D4; i += 32) {
        float4 wv = w4[i];
        float4 qv = q4[i];
        s += wv.x * qv.x + wv.y * qv.y + wv.z * qv.z + wv.w * qv.w;
    }
    #pragma unroll
    for (int o = 16; o > 0; o >>= 1) s += __shfl_xor_sync(0xFFFFFFFFu, s, o);

    if (lane == 0) {
        float x = s + b[warp];
        g_gated[warp] = 1.0f / (1.0f + expf(-x));
    }
}

// ---------------------------------------------------------------------------
// Kernel 2: sims[n] = 1 - (1/D) * sum_k |memory[n,k] - gated[k]|
//           mask[n] = sims[n] >= 0.8
// One warp per pattern n. gated staged in shared memory (avoids 256 MB of
// redundant L2 traffic that would push us past the LTS cap).
// ---------------------------------------------------------------------------
__global__ void sim_kernel(const float* __restrict__ mem,
                           float* __restrict__ out,
                           int N, int D, int writeMask) {
    extern __shared__ float sg[];  // D floats
    int D4 = D >> 2;

    // Cooperative load of gated into smem (vectorized).
    const float4* g4 = reinterpret_cast<const float4*>(g_gated);
    float4* sg4 = reinterpret_cast<float4*>(sg);
    for (int i = threadIdx.x; i < D4; i += blockDim.x) sg4[i] = g4[i];
    __syncthreads();

    int warp = (blockIdx.x * blockDim.x + threadIdx.x) >> 5;
    int lane = threadIdx.x & 31;
    if (warp >= N) return;

    const float4* m4 = reinterpret_cast<const float4*>(mem + (size_t)warp * D);

    float s = 0.0f;
    #pragma unroll 4
    for (int i = lane; i < D4; i += 32) {
        float4 mv = m4[i];
        float4 gv = sg4[i];
        s += fabsf(mv.x - gv.x) + fabsf(mv.y - gv.y)
           + fabsf(mv.z - gv.z) + fabsf(mv.w - gv.w);
    }
    #pragma unroll
    for (int o = 16; o > 0; o >>= 1) s += __shfl_xor_sync(0xFFFFFFFFu, s, o);

    if (lane == 0) {
        float sim = 1.0f - s * (1.0f / (float)D);
        out[warp] = sim;
        if (writeMask) out[N + warp] = (sim >= 0.8f) ? 1.0f : 0.0f;
    }
}

// ---------------------------------------------------------------------------
// Launch contract
// Inputs (metadata order): query [1,D] f32, W [D,D] f32, b [D] f32,
//                          memory [N,D] f32.
// Output: sims [N] f32, then mask [N] as 0/1 f32 if out_size >= 2N.
// ---------------------------------------------------------------------------
extern "C" void kernel_launch(void* const* d_in, const int* in_sizes, int n_in,
                              void* d_out, int out_size) {
    const float* q   = (const float*)d_in[0];
    const float* W   = (const float*)d_in[1];
    const float* b   = (const float*)d_in[2];
    const float* mem = (const float*)d_in[3];
    float* out = (float*)d_out;

    int D = in_sizes[0];              // 4096
    int N = in_sizes[3] / D;          // 16384
    int writeMask = (out_size >= 2 * N) ? 1 : 0;

    // Kernel 1: one warp per row -> D warps; 256 threads = 8 warps/block.
    {
        int warpsPerBlock = 8;
        int blocks = (D + warpsPerBlock - 1) / warpsPerBlock;
        gate_kernel<<<blocks, 256>>>(q, W, b, D);
    }

    // Kernel 2: one warp per pattern -> N warps; 16 KB dynamic smem for gated.
    {
        int warpsPerBlock = 8;
        int blocks = (N + warpsPerBlock - 1) / warpsPerBlock;
        size_t smem = (size_t)D * sizeof(float);
        sim_kernel<<<blocks, 256, smem>>>(mem, out, N, D, writeMask);
    }
}